// round 5
// baseline (speedup 1.0000x reference)
#include <cuda_runtime.h>

#define L_SEQ 256
#define D_HEAD 64
#define MASK_VAL (-4294967295.0f)   // -2^32 + 1
#define MAX_BHQ (4 * 8 * 256)

// Scratch: E0[bhq][k] = 0.125*(Q[q].K[k]) + AM[q][k]
__device__ float g_E0[(size_t)MAX_BHQ * L_SEQ];

__device__ __forceinline__ void stcs_f(float* p, float v) {
    asm volatile("st.global.cs.f32 [%0], %1;" :: "l"(p), "f"(v) : "memory");
}

// ---------------- Pre-kernel: E0 = Q@K^T * 0.125 + AM ----------------
__global__ __launch_bounds__(256, 8)
void e0_kernel(const float* __restrict__ Q,
               const float* __restrict__ Km,
               const float* __restrict__ AM)
{
    const int bhq = blockIdx.x;
    const int q   = bhq & (L_SEQ - 1);
    const int bh  = bhq >> 8;

    __shared__ float qsh[D_HEAD];
    __shared__ float esh[L_SEQ];

    const int tid  = threadIdx.x;
    const int w    = tid >> 5;
    const int lane = tid & 31;
    const int f4   = lane & 15;
    const int grp  = lane >> 4;

    if (tid < D_HEAD) qsh[tid] = Q[(size_t)bhq * D_HEAD + tid];
    __syncthreads();

    const float4 q4 = ((const float4*)qsh)[f4];
    const int krow0 = 2 * w + grp;
    const float4* kptr = (const float4*)(Km + (size_t)bh * L_SEQ * D_HEAD)
                         + (krow0 * 16 + f4);
    const float* amrow = AM + q * L_SEQ;

    #pragma unroll 4
    for (int it = 0; it < L_SEQ / 16; ++it) {
        float4 kk = __ldg(kptr);
        kptr += 256;
        float s = kk.x * q4.x + kk.y * q4.y + kk.z * q4.z + kk.w * q4.w;
        s += __shfl_xor_sync(0xffffffffu, s, 1);
        s += __shfl_xor_sync(0xffffffffu, s, 2);
        s += __shfl_xor_sync(0xffffffffu, s, 4);
        s += __shfl_xor_sync(0xffffffffu, s, 8);
        if (f4 == 0) {
            const int k = it * 16 + krow0;
            esh[k] = s * 0.125f + amrow[k];
        }
    }
    __syncthreads();
    g_E0[(size_t)bhq * L_SEQ + tid] = esh[tid];   // coalesced
}

// ---------------- Main kernel ----------------
// One CTA per (b, h, q) row. 256 threads, 7 CTAs/SM.
__global__ __launch_bounds__(256, 7)
void tasdp_kernel(const float* __restrict__ V,
                  const float* __restrict__ TMK,
                  const float* __restrict__ TMV,
                  const float* __restrict__ Q,
                  const unsigned char* __restrict__ PM,  // padding_mask [b,L]
                  float* __restrict__ O,                 // [b,h,L,D]
                  float* __restrict__ AW,                // [b,h,L,L]
                  int H, int write_aw)
{
    const int bhq = blockIdx.x;
    const int bh  = bhq >> 8;
    const int b   = bh / H;

    __shared__ float  qsh[D_HEAD];
    __shared__ float  esh[L_SEQ];
    __shared__ float  red[8];
    __shared__ float4 acc_sh[16][16];

    const int tid  = threadIdx.x;
    const int w    = tid >> 5;
    const int lane = tid & 31;
    const int f4   = lane & 15;
    const int grp  = lane >> 4;

    if (tid < D_HEAD) qsh[tid] = Q[(size_t)bhq * D_HEAD + tid];
    __syncthreads();

    // ---- Phase A: energy[k] = 0.125*(TMK[q,k].Q[q]) + E0[q,k], PM override ----
    const float4 q4 = ((const float4*)qsh)[f4];
    const int krow0 = 2 * w + grp;
    const float4* tptr = (const float4*)(TMK + (size_t)bhq * L_SEQ * D_HEAD)
                         + (krow0 * 16 + f4);
    const float*         e0row = g_E0 + (size_t)bhq * L_SEQ;
    const unsigned char* pmrow = PM + b * L_SEQ;

    #pragma unroll 4
    for (int it = 0; it < L_SEQ / 16; ++it) {
        float4 t = __ldcs(tptr);           // streaming, no reuse
        tptr += 256;                       // 16 rows * 16 float4
        float s = t.x * q4.x + t.y * q4.y + t.z * q4.z + t.w * q4.w;
        s += __shfl_xor_sync(0xffffffffu, s, 1);
        s += __shfl_xor_sync(0xffffffffu, s, 2);
        s += __shfl_xor_sync(0xffffffffu, s, 4);
        s += __shfl_xor_sync(0xffffffffu, s, 8);
        if (f4 == 0) {
            const int k = it * 16 + krow0;
            float e = s * 0.125f + e0row[k];
            if (pmrow[k]) e = MASK_VAL;
            esh[k] = e;
        }
    }
    __syncthreads();

    // ---- Softmax over k ----
    const float v = esh[tid];
    float m = v;
    #pragma unroll
    for (int o = 16; o > 0; o >>= 1)
        m = fmaxf(m, __shfl_xor_sync(0xffffffffu, m, o));
    if (lane == 0) red[w] = m;
    __syncthreads();
    if (tid == 0) {
        float mm = red[0];
        #pragma unroll
        for (int i = 1; i < 8; ++i) mm = fmaxf(mm, red[i]);
        red[0] = mm;
    }
    __syncthreads();
    m = red[0];
    __syncthreads();

    const float e = __expf(v - m);
    float s = e;
    #pragma unroll
    for (int o = 16; o > 0; o >>= 1)
        s += __shfl_xor_sync(0xffffffffu, s, o);
    if (lane == 0) red[w] = s;
    __syncthreads();
    if (tid == 0) {
        float ss = red[0];
        #pragma unroll
        for (int i = 1; i < 8; ++i) ss += red[i];
        red[0] = 1.0f / ss;
    }
    __syncthreads();
    const float a = e * red[0];
    __syncthreads();
    esh[tid] = a;
    if (write_aw) stcs_f(AW + (size_t)bhq * L_SEQ + tid, a);
    __syncthreads();

    // ---- Phase B: O[q,:] = sum_k a[k] * (V[k,:] + TMV[q,k,:]) ----
    const int bf4 = tid & 15;
    const int kg  = tid >> 4;
    float4 acc = make_float4(0.f, 0.f, 0.f, 0.f);
    const float4* tvp = (const float4*)(TMV + (size_t)bhq * L_SEQ * D_HEAD)
                        + (kg * 16 + bf4);
    const float4* vvp = (const float4*)(V   + (size_t)bh  * L_SEQ * D_HEAD)
                        + (kg * 16 + bf4);

    #pragma unroll 4
    for (int k = kg; k < L_SEQ; k += 16) {
        const float ak = esh[k];
        float4 t  = __ldcs(tvp);
        float4 vv = __ldg(vvp);
        tvp += 256;
        vvp += 256;
        acc.x += ak * (t.x + vv.x);
        acc.y += ak * (t.y + vv.y);
        acc.z += ak * (t.z + vv.z);
        acc.w += ak * (t.w + vv.w);
    }
    acc_sh[kg][bf4] = acc;
    __syncthreads();

    if (tid < 16) {
        float4 r = acc_sh[0][tid];
        #pragma unroll
        for (int g = 1; g < 16; ++g) {
            float4 p = acc_sh[g][tid];
            r.x += p.x; r.y += p.y; r.z += p.z; r.w += p.w;
        }
        ((float4*)(O + (size_t)bhq * D_HEAD))[tid] = r;
    }
}

extern "C" void kernel_launch(void* const* d_in, const int* in_sizes, int n_in,
                              void* d_out, int out_size)
{
    const float*         Q   = (const float*)d_in[0];
    const float*         Km  = (const float*)d_in[1];
    const float*         V   = (const float*)d_in[2];
    const float*         TMK = (const float*)d_in[3];
    const float*         TMV = (const float*)d_in[4];
    const float*         AM  = (const float*)d_in[5];
    const unsigned char* PM  = (const unsigned char*)d_in[6];

    const int L = 256, D = 64;
    const int b = in_sizes[6] / L;                 // padding_mask is [b, L]
    const int h = in_sizes[0] / (b * L * D);       // Q is [b, h, L, D]

    const int nO  = b * h * L * D;
    const int nAW = b * h * L * L;

    float* O  = (float*)d_out;
    float* AW = O + nO;
    const int write_aw = (out_size >= nO + nAW) ? 1 : 0;

    e0_kernel<<<b * h * L, 256>>>(Q, Km, AM);
    tasdp_kernel<<<b * h * L, 256>>>(V, TMK, TMV, Q, PM, O, AW, h, write_aw);
}

// round 6
// speedup vs baseline: 1.2517x; 1.2517x over previous
#include <cuda_runtime.h>

#define L_SEQ 256
#define D_HEAD 64
#define MASK_VAL (-4294967295.0f)   // -2^32 + 1

__device__ __forceinline__ void stcs_f(float* p, float v) {
    asm volatile("st.global.cs.f32 [%0], %1;" :: "l"(p), "f"(v) : "memory");
}

// One CTA per (b, h, q) row. 256 threads, 6 CTAs/SM.
// Single-pass: energy + online-softmax + value aggregation fused per k row.
__global__ __launch_bounds__(256, 6)
void tasdp_kernel(const float* __restrict__ Q,
                  const float* __restrict__ Km,
                  const float* __restrict__ V,
                  const float* __restrict__ TMK,
                  const float* __restrict__ TMV,
                  const float* __restrict__ AM,          // attn_mask [L,L]
                  const unsigned char* __restrict__ PM,  // padding_mask [b,L]
                  float* __restrict__ O,                 // [b,h,L,D]
                  float* __restrict__ AW,                // [b,h,L,L]
                  int H, int write_aw)
{
    const int bhq = blockIdx.x;          // b*h*L + q
    const int q   = bhq & (L_SEQ - 1);
    const int bh  = bhq >> 8;
    const int b   = bh / H;

    __shared__ float  qsh[D_HEAD];
    __shared__ float  esh[L_SEQ];
    __shared__ float  red[8];
    __shared__ float4 acc_sh[16][16];

    const int tid  = threadIdx.x;
    const int w    = tid >> 5;
    const int lane = tid & 31;
    const int f4   = lane & 15;          // float4 chunk within d (16*4 = 64)
    const int grp  = lane >> 4;          // which of 2 k-rows this half-warp owns

    if (tid < D_HEAD) qsh[tid] = Q[(size_t)bhq * D_HEAD + tid];
    __syncthreads();

    // ---- Single fused pass over k ----
    // Half-warp hw = 2w+grp owns k in {hw, hw+16, ..., hw+240}.
    const float4 q4 = ((const float4*)qsh)[f4];
    const int hw = 2 * w + grp;
    const size_t roff = (size_t)hw * 16 + f4;
    const float4* tkp = (const float4*)(TMK + (size_t)bhq * L_SEQ * D_HEAD) + roff;
    const float4* kkp = (const float4*)(Km  + (size_t)bh  * L_SEQ * D_HEAD) + roff;
    const float4* tvp = (const float4*)(TMV + (size_t)bhq * L_SEQ * D_HEAD) + roff;
    const float4* vvp = (const float4*)(V   + (size_t)bh  * L_SEQ * D_HEAD) + roff;
    const float*         amrow = AM + q * L_SEQ;
    const unsigned char* pmrow = PM + b * L_SEQ;

    float  m_run = MASK_VAL;
    float4 acc   = make_float4(0.f, 0.f, 0.f, 0.f);

    #pragma unroll 2
    for (int it = 0; it < L_SEQ / 16; ++it) {
        // 4 independent loads — issue together, maximize MLP
        float4 t  = __ldcs(tkp);   // TMK: streaming
        float4 kx = __ldg (kkp);   // K:   L2-hot
        float4 tv = __ldcs(tvp);   // TMV: streaming
        float4 vx = __ldg (vvp);   // V:   L2-hot
        tkp += 256; kkp += 256; tvp += 256; vvp += 256;

        // energy for this half-warp's k row
        float s = (t.x + kx.x) * q4.x + (t.y + kx.y) * q4.y
                + (t.z + kx.z) * q4.z + (t.w + kx.w) * q4.w;
        s += __shfl_xor_sync(0xffffffffu, s, 1);
        s += __shfl_xor_sync(0xffffffffu, s, 2);
        s += __shfl_xor_sync(0xffffffffu, s, 4);
        s += __shfl_xor_sync(0xffffffffu, s, 8);   // all 16 lanes hold full sum

        const int k = it * 16 + hw;
        float e = s * 0.125f + amrow[k];           // 1/sqrt(64)
        if (pmrow[k]) e = MASK_VAL;
        if (f4 == 0) esh[k] = e;

        // online softmax update
        const float m_new = fmaxf(m_run, e);
        const float c = __expf(m_run - m_new);     // rescale old acc
        const float p = __expf(e - m_new);         // weight of this k
        m_run = m_new;
        acc.x = acc.x * c + p * (tv.x + vx.x);
        acc.y = acc.y * c + p * (tv.y + vx.y);
        acc.z = acc.z * c + p * (tv.z + vx.z);
        acc.w = acc.w * c + p * (tv.w + vx.w);
    }
    __syncthreads();

    // ---- Final softmax normalization from cached energies ----
    const float v = esh[tid];
    float m = v;
    #pragma unroll
    for (int o = 16; o > 0; o >>= 1)
        m = fmaxf(m, __shfl_xor_sync(0xffffffffu, m, o));
    if (lane == 0) red[w] = m;
    __syncthreads();
    if (tid == 0) {
        float mm = red[0];
        #pragma unroll
        for (int i = 1; i < 8; ++i) mm = fmaxf(mm, red[i]);
        red[0] = mm;
    }
    __syncthreads();
    m = red[0];                                    // global max
    __syncthreads();

    const float pe = __expf(v - m);
    float ssum = pe;
    #pragma unroll
    for (int o = 16; o > 0; o >>= 1)
        ssum += __shfl_xor_sync(0xffffffffu, ssum, o);
    if (lane == 0) red[w] = ssum;
    __syncthreads();
    if (tid == 0) {
        float z = red[0];
        #pragma unroll
        for (int i = 1; i < 8; ++i) z += red[i];
        red[1] = 1.0f / z;
    }
    __syncthreads();
    const float invZ = red[1];

    if (write_aw) stcs_f(AW + (size_t)bhq * L_SEQ + tid, pe * invZ);

    // ---- Combine the 16 half-warp accumulators ----
    const float factor = __expf(m_run - m) * invZ;
    acc.x *= factor; acc.y *= factor; acc.z *= factor; acc.w *= factor;
    acc_sh[hw][f4] = acc;                          // lanes with same (hw,f4) write same value
    __syncthreads();

    if (tid < 16) {
        float4 r = acc_sh[0][tid];
        #pragma unroll
        for (int g = 1; g < 16; ++g) {
            float4 p4 = acc_sh[g][tid];
            r.x += p4.x; r.y += p4.y; r.z += p4.z; r.w += p4.w;
        }
        ((float4*)(O + (size_t)bhq * D_HEAD))[tid] = r;
    }
}

extern "C" void kernel_launch(void* const* d_in, const int* in_sizes, int n_in,
                              void* d_out, int out_size)
{
    const float*         Q   = (const float*)d_in[0];
    const float*         Km  = (const float*)d_in[1];
    const float*         V   = (const float*)d_in[2];
    const float*         TMK = (const float*)d_in[3];
    const float*         TMV = (const float*)d_in[4];
    const float*         AM  = (const float*)d_in[5];
    const unsigned char* PM  = (const unsigned char*)d_in[6];

    const int L = 256, D = 64;
    const int b = in_sizes[6] / L;                 // padding_mask is [b, L]
    const int h = in_sizes[0] / (b * L * D);       // Q is [b, h, L, D]

    const int nO  = b * h * L * D;
    const int nAW = b * h * L * L;

    float* O  = (float*)d_out;
    float* AW = O + nO;
    const int write_aw = (out_size >= nO + nAW) ? 1 : 0;

    tasdp_kernel<<<b * h * L, 256>>>(Q, Km, V, TMK, TMV, AM, PM, O, AW, h, write_aw);
}

// round 7
// speedup vs baseline: 1.2974x; 1.0365x over previous
#include <cuda_runtime.h>

#define L_SEQ 256
#define D_HEAD 64
#define MASK_VAL (-4294967295.0f)   // -2^32 + 1

__device__ __forceinline__ void stcs_f(float* p, float v) {
    asm volatile("st.global.cs.f32 [%0], %1;" :: "l"(p), "f"(v) : "memory");
}

// Persistent CTAs, 256 threads, 6 CTAs/SM. Each CTA grid-strides over (b,h,q) rows.
__global__ __launch_bounds__(256, 6)
void tasdp_kernel(const float* __restrict__ Q,
                  const float* __restrict__ Km,
                  const float* __restrict__ V,
                  const float* __restrict__ TMK,
                  const float* __restrict__ TMV,
                  const float* __restrict__ AM,          // attn_mask [L,L]
                  const unsigned char* __restrict__ PM,  // padding_mask [b,L]
                  float* __restrict__ O,                 // [b,h,L,D]
                  float* __restrict__ AW,                // [b,h,L,L]
                  int H, int write_aw, int total)
{
    __shared__ float  qsh[D_HEAD];
    __shared__ float  esh[L_SEQ];
    __shared__ float  red_m[8];
    __shared__ float  red_s[8];
    __shared__ float  gred[2];
    __shared__ float4 acc_sh[16][16];

    const int tid  = threadIdx.x;
    const int w    = tid >> 5;
    const int lane = tid & 31;
    const int f4   = lane & 15;          // float4 chunk within d (16*4 = 64)
    const int grp  = lane >> 4;
    const int krow0 = 2 * w + grp;       // this half-warp's first k row

    for (int bhq = blockIdx.x; bhq < total; bhq += gridDim.x) {
        const int q  = bhq & (L_SEQ - 1);
        const int bh = bhq >> 8;
        const int b  = bh / H;

        if (tid < D_HEAD) qsh[tid] = Q[(size_t)bhq * D_HEAD + tid];
        __syncthreads();                                   // (1)

        // ---- Phase A: energy[k] = ((K[k]+TMK[q,k]).Q[q])/8 + AM, PM override ----
        const float4 q4 = ((const float4*)qsh)[f4];
        const float4* tptr = (const float4*)(TMK + (size_t)bhq * L_SEQ * D_HEAD)
                             + (krow0 * 16 + f4);
        const float4* kptr = (const float4*)(Km  + (size_t)bh  * L_SEQ * D_HEAD)
                             + (krow0 * 16 + f4);
        const float*         amrow = AM + q * L_SEQ;
        const unsigned char* pmrow = PM + b * L_SEQ;

        #pragma unroll 4
        for (int it = 0; it < L_SEQ / 16; ++it) {
            float4 t  = __ldcs(tptr);      // streaming, no reuse
            float4 kk = __ldg(kptr);       // hot in L2
            tptr += 256;                   // 16 rows * 16 float4
            kptr += 256;
            float s = (t.x + kk.x) * q4.x + (t.y + kk.y) * q4.y
                    + (t.z + kk.z) * q4.z + (t.w + kk.w) * q4.w;
            s += __shfl_xor_sync(0xffffffffu, s, 1);
            s += __shfl_xor_sync(0xffffffffu, s, 2);
            s += __shfl_xor_sync(0xffffffffu, s, 4);
            s += __shfl_xor_sync(0xffffffffu, s, 8);
            if (f4 == 0) {
                const int k = it * 16 + krow0;
                float e = s * 0.125f + amrow[k];
                if (pmrow[k]) e = MASK_VAL;
                esh[k] = e;
            }
        }
        __syncthreads();                                   // (2)

        // ---- Softmax: two-level online combine (4 barriers total) ----
        const float v = esh[tid];
        float wm = v;
        #pragma unroll
        for (int o = 16; o > 0; o >>= 1)
            wm = fmaxf(wm, __shfl_xor_sync(0xffffffffu, wm, o));
        float ws = __expf(v - wm);
        #pragma unroll
        for (int o = 16; o > 0; o >>= 1)
            ws += __shfl_xor_sync(0xffffffffu, ws, o);
        if (lane == 0) { red_m[w] = wm; red_s[w] = ws; }
        __syncthreads();                                   // (3)

        if (w == 0) {
            float mi = (lane < 8) ? red_m[lane] : MASK_VAL;
            float si = (lane < 8) ? red_s[lane] : 0.0f;
            float gm = mi;
            #pragma unroll
            for (int o = 4; o > 0; o >>= 1)
                gm = fmaxf(gm, __shfl_xor_sync(0xffffffffu, gm, o));
            float z = si * __expf(mi - gm);
            #pragma unroll
            for (int o = 4; o > 0; o >>= 1)
                z += __shfl_xor_sync(0xffffffffu, z, o);
            if (lane == 0) { gred[0] = gm; gred[1] = 1.0f / z; }
        }
        __syncthreads();                                   // (4)

        const float m    = gred[0];
        const float invZ = gred[1];
        const float a    = __expf(v - m) * invZ;
        esh[tid] = a;
        if (write_aw) stcs_f(AW + (size_t)bhq * L_SEQ + tid, a);
        __syncthreads();                                   // (5)

        // ---- Phase B: O[q,:] = sum_k a[k] * (V[k,:] + TMV[q,k,:]) ----
        const int bf4 = tid & 15;
        const int kg  = tid >> 4;
        float4 acc = make_float4(0.f, 0.f, 0.f, 0.f);
        const float4* tvp = (const float4*)(TMV + (size_t)bhq * L_SEQ * D_HEAD)
                            + (kg * 16 + bf4);
        const float4* vvp = (const float4*)(V   + (size_t)bh  * L_SEQ * D_HEAD)
                            + (kg * 16 + bf4);

        #pragma unroll 4
        for (int k = kg; k < L_SEQ; k += 16) {
            const float ak = esh[k];
            float4 t  = __ldcs(tvp);
            float4 vv = __ldg(vvp);
            tvp += 256;
            vvp += 256;
            acc.x += ak * (t.x + vv.x);
            acc.y += ak * (t.y + vv.y);
            acc.z += ak * (t.z + vv.z);
            acc.w += ak * (t.w + vv.w);
        }
        acc_sh[kg][bf4] = acc;
        __syncthreads();                                   // (6)

        if (tid < 16) {
            float4 r = acc_sh[0][tid];
            #pragma unroll
            for (int g = 1; g < 16; ++g) {
                float4 p = acc_sh[g][tid];
                r.x += p.x; r.y += p.y; r.z += p.z; r.w += p.w;
            }
            ((float4*)(O + (size_t)bhq * D_HEAD))[tid] = r;
        }
        // next iteration's barrier (1) protects acc_sh/esh reuse
    }
}

extern "C" void kernel_launch(void* const* d_in, const int* in_sizes, int n_in,
                              void* d_out, int out_size)
{
    const float*         Q   = (const float*)d_in[0];
    const float*         Km  = (const float*)d_in[1];
    const float*         V   = (const float*)d_in[2];
    const float*         TMK = (const float*)d_in[3];
    const float*         TMV = (const float*)d_in[4];
    const float*         AM  = (const float*)d_in[5];
    const unsigned char* PM  = (const unsigned char*)d_in[6];

    const int L = 256, D = 64;
    const int b = in_sizes[6] / L;                 // padding_mask is [b, L]
    const int h = in_sizes[0] / (b * L * D);       // Q is [b, h, L, D]

    const int nO  = b * h * L * D;
    const int nAW = b * h * L * L;
    const int total = b * h * L;

    float* O  = (float*)d_out;
    float* AW = O + nO;
    const int write_aw = (out_size >= nO + nAW) ? 1 : 0;

    int sms = 148;
    cudaDeviceGetAttribute(&sms, cudaDevAttrMultiProcessorCount, 0);
    int grid = sms * 6;
    if (grid > total) grid = total;

    tasdp_kernel<<<grid, 256>>>(Q, Km, V, TMK, TMV, AM, PM, O, AW, h, write_aw, total);
}